// round 5
// baseline (speedup 1.0000x reference)
#include <cuda_runtime.h>

// ---------------------------------------------------------------------------
// Problem constants: B=4, S=2048, E=1024, H=1, hd=1024
//
// Numerics strategy (reference is pure fp32 JAX/XLA, unknown reduction order):
//   - The pruning masks are rank-based (norm >= median) and ulp-sensitive.
//     Everything feeding the masks (qkv GEMM, tile norms, row norms, median)
//     is computed with fp64 accumulation and rounded ONCE to fp32 — the
//     minimax-distance point to any fp32-ordered reference computation.
//   - Everything downstream of the masks is smooth; plain fp32 SIMT GEMMs.
// ---------------------------------------------------------------------------
#define BB 4
#define SS 2048
#define EE 1024

// Scratch layout (floats) inside one big __device__ array.
#define OFF_QKV   0L                          // 4*2048*3072 = 25165824
#define OFF_Q1    (OFF_QKV + 25165824L)       // q_  4*2048*2048 = 16777216
#define OFF_K1    (OFF_Q1  + 16777216L)       // k_
#define OFF_PC    (OFF_K1  + 16777216L)       // precompute
#define OFF_SC    (OFF_PC  + 16777216L)       // scale_values
#define OFF_PO    (OFF_SC  + 16777216L)       // preoutput 4*2048*1024 = 8388608
#define OFF_WOM   (OFF_PO  + 8388608L)        // masked WO 8388608
#define OFF_NQ    (OFF_WOM + 8388608L)        // tile norms q 4*1024*512 = 2097152
#define OFF_NK    (OFF_NQ  + 2097152L)        // tile norms k
#define OFF_NW    (OFF_NK  + 2097152L)        // row norms WO 4*2048 = 8192
#define OFF_OST   (OFF_NW  + 8192L)           // 24 order statistics
#define SCRATCH_TOTAL (OFF_OST + 32L)

__device__ float g_scratch[SCRATCH_TOTAL];

// ---------------------------------------------------------------------------
// qkv GEMM with fp64 accumulation (exact products, order-independent to
// fp32 ulp): C[m,n] = round_f32( sum_k (double)A[m,k]*(double)B[n,k] + bias )
// A: 8192x1024 row-major, B(=Wqkv): 3072x1024 row-major, C: 8192x3072.
// Block 64x64, 256 threads, 4x4 doubles per thread, K-panel 16.
// ---------------------------------------------------------------------------
__global__ __launch_bounds__(256)
void gemm_f64acc_k(const float* __restrict__ A, const float* __restrict__ B,
                   float* __restrict__ C, const float* __restrict__ bias)
{
    __shared__ float As[16][64];
    __shared__ float Bs[16][64];

    const int tid = threadIdx.x;
    const int bm  = blockIdx.y * 64;
    const int bn  = blockIdx.x * 64;
    const int tx  = tid & 15;           // N dir, 0..15
    const int ty  = tid >> 4;           // M dir, 0..15
    const int lrow = tid >> 2;          // 0..63
    const int lcol = (tid & 3) * 4;     // 0,4,8,12

    double acc[4][4];
#pragma unroll
    for (int i = 0; i < 4; i++)
#pragma unroll
        for (int j = 0; j < 4; j++) acc[i][j] = 0.0;

    for (int k0 = 0; k0 < 1024; k0 += 16) {
        float4 av = *(const float4*)(A + (long)(bm + lrow) * 1024 + k0 + lcol);
        // store transposed into [k][m]
        As[lcol + 0][lrow] = av.x;
        As[lcol + 1][lrow] = av.y;
        As[lcol + 2][lrow] = av.z;
        As[lcol + 3][lrow] = av.w;
        float4 bv = *(const float4*)(B + (long)(bn + lrow) * 1024 + k0 + lcol);
        Bs[lcol + 0][lrow] = bv.x;
        Bs[lcol + 1][lrow] = bv.y;
        Bs[lcol + 2][lrow] = bv.z;
        Bs[lcol + 3][lrow] = bv.w;
        __syncthreads();
#pragma unroll
        for (int kk = 0; kk < 16; ++kk) {
            double a[4], b[4];
#pragma unroll
            for (int i = 0; i < 4; i++) a[i] = (double)As[kk][ty * 4 + i];
#pragma unroll
            for (int j = 0; j < 4; j++) b[j] = (double)Bs[kk][tx * 4 + j];
#pragma unroll
            for (int i = 0; i < 4; i++)
#pragma unroll
                for (int j = 0; j < 4; j++)
                    acc[i][j] = fma(a[i], b[j], acc[i][j]);
        }
        __syncthreads();
    }

#pragma unroll
    for (int i = 0; i < 4; i++) {
        float* crow = C + (long)(bm + ty * 4 + i) * 3072 + bn + tx * 4;
#pragma unroll
        for (int j = 0; j < 4; j++)
            crow[j] = (float)(acc[i][j] + (double)bias[bn + tx * 4 + j]);
    }
}

// ---------------------------------------------------------------------------
// Plain fp32 tiled GEMM: C = alpha * A * op(B)
// A: M x K row-major (lda), B: TRANSB ? (N x K, ldb) : (K x N, ldb)
// C: M x N row-major (ldc). Batched via blockIdx.z with element strides.
// M, N multiples of 128; K multiple of 8. 256 threads, 8x8 per thread.
// ---------------------------------------------------------------------------
template<bool TRANSB>
__global__ __launch_bounds__(256)
void gemm_k(const float* __restrict__ A, const float* __restrict__ B,
            float* __restrict__ C,
            int M, int N, int K, int lda, int ldb, int ldc,
            long sA, long sB, long sC, float alpha)
{
    const int bz = blockIdx.z;
    A += (long)bz * sA;
    B += (long)bz * sB;
    C += (long)bz * sC;

    __shared__ float As[8][128];
    __shared__ float Bs[8][128];

    const int tid  = threadIdx.x;
    const int bm   = blockIdx.y * 128;
    const int bn   = blockIdx.x * 128;
    const int tx   = tid & 15;          // 0..15 (N direction)
    const int ty   = tid >> 4;          // 0..15 (M direction)
    const int arow = tid >> 1;          // 0..127
    const int acol = (tid & 1) * 4;     // 0 or 4
    const int brow = tid >> 5;          // 0..7  (NN layout)
    const int bcol = (tid & 31) * 4;    // 0..124

    float acc[8][8];
#pragma unroll
    for (int i = 0; i < 8; i++)
#pragma unroll
        for (int j = 0; j < 8; j++) acc[i][j] = 0.0f;

    for (int k0 = 0; k0 < K; k0 += 8) {
        float4 av = *(const float4*)(A + (long)(bm + arow) * lda + k0 + acol);
        As[acol + 0][arow] = av.x;
        As[acol + 1][arow] = av.y;
        As[acol + 2][arow] = av.z;
        As[acol + 3][arow] = av.w;
        if (TRANSB) {
            float4 bv = *(const float4*)(B + (long)(bn + arow) * ldb + k0 + acol);
            Bs[acol + 0][arow] = bv.x;
            Bs[acol + 1][arow] = bv.y;
            Bs[acol + 2][arow] = bv.z;
            Bs[acol + 3][arow] = bv.w;
        } else {
            float4 bv = *(const float4*)(B + (long)(k0 + brow) * ldb + bn + bcol);
            *(float4*)&Bs[brow][bcol] = bv;
        }
        __syncthreads();
#pragma unroll
        for (int kk = 0; kk < 8; ++kk) {
            float4 a0 = *(const float4*)&As[kk][ty * 8];
            float4 a1 = *(const float4*)&As[kk][ty * 8 + 4];
            float4 b0 = *(const float4*)&Bs[kk][tx * 8];
            float4 b1 = *(const float4*)&Bs[kk][tx * 8 + 4];
            float a[8] = {a0.x, a0.y, a0.z, a0.w, a1.x, a1.y, a1.z, a1.w};
            float b[8] = {b0.x, b0.y, b0.z, b0.w, b1.x, b1.y, b1.z, b1.w};
#pragma unroll
            for (int i = 0; i < 8; i++)
#pragma unroll
                for (int j = 0; j < 8; j++)
                    acc[i][j] = fmaf(a[i], b[j], acc[i][j]);
        }
        __syncthreads();
    }

#pragma unroll
    for (int i = 0; i < 8; i++) {
        float* crow = C + (long)(bm + ty * 8 + i) * ldc + bn + tx * 8;
#pragma unroll
        for (int j = 0; j < 8; j++)
            crow[j] = acc[i][j] * alpha;
    }
}

// ---------------------------------------------------------------------------
// Tile norms for q and k (fp64 exact, rounded once to fp32).
// qkv is (B, S, 3E) row-major; q at col 0, k at 1024.
// Tiles are 2x2 over (S, D): norms shape (B, 1024, 512) per tensor.
// ---------------------------------------------------------------------------
__global__ void tile_norm_k(const float* __restrict__ qkv,
                            float* __restrict__ nq, float* __restrict__ nk)
{
    long idx = (long)blockIdx.x * blockDim.x + threadIdx.x;   // 2 * 2097152
    if (idx >= 2L * 2097152L) return;
    int tensor = (idx >= 2097152L) ? 1 : 0;
    long t = idx - (long)tensor * 2097152L;
    int b   = (int)(t / (1024 * 512));
    int rem = (int)(t % (1024 * 512));
    int ts  = rem / 512;
    int td  = rem % 512;
    const float* p = qkv + (long)b * SS * 3072 + (long)(2 * ts) * 3072
                         + tensor * 1024 + 2 * td;
    double v00 = p[0], v01 = p[1], v10 = p[3072], v11 = p[3073];
    double n = sqrt(v00 * v00 + v01 * v01 + v10 * v10 + v11 * v11);
    (tensor ? nk : nq)[t] = (float)n;
}

// ---------------------------------------------------------------------------
// Row norms of WO (fp64 exact): (B*S) rows of 1024. One block per row.
// ---------------------------------------------------------------------------
__global__ void row_norm_k(const float* __restrict__ WO, float* __restrict__ nw)
{
    int row = blockIdx.x;                       // 0..8191
    const float* p = WO + (long)row * 1024;
    double s = 0.0;
    for (int i = threadIdx.x; i < 1024; i += 256) {
        double v = p[i];
        s += v * v;
    }
    __shared__ double red[256];
    red[threadIdx.x] = s;
    __syncthreads();
    for (int off = 128; off > 0; off >>= 1) {
        if (threadIdx.x < off) red[threadIdx.x] += red[threadIdx.x + off];
        __syncthreads();
    }
    if (threadIdx.x == 0) nw[row] = (float)sqrt(red[0]);
}

// ---------------------------------------------------------------------------
// Exact order-statistic via MSB-first byte radix select.
// Nonnegative float bits are order-preserving as uint32.
// 24 blocks: problem = blockIdx.x/2, rank offset = blockIdx.x%2.
//   problems 0..3  : nq per batch, n=524288, ranks 262143 / 262144
//   problems 4..7  : nk per batch, n=524288
//   problems 8..11 : nw per batch, n=2048,  ranks 1023 / 1024
// ---------------------------------------------------------------------------
__global__ void select_k(const float* __restrict__ nq, const float* __restrict__ nk,
                         const float* __restrict__ nw, float* __restrict__ ostat)
{
    int pid   = blockIdx.x >> 1;
    int which = blockIdx.x & 1;
    const float* data;
    long n, rank;
    if (pid < 4)       { data = nq + (long)pid * 524288L;       n = 524288; rank = 262143 + which; }
    else if (pid < 8)  { data = nk + (long)(pid - 4) * 524288L; n = 524288; rank = 262143 + which; }
    else               { data = nw + (long)(pid - 8) * 2048L;   n = 2048;   rank = 1023 + which; }

    __shared__ unsigned int hist[256];
    __shared__ unsigned int s_sel;
    __shared__ long s_rank;
    if (threadIdx.x == 0) s_rank = rank;

    unsigned prefix = 0u, pmask = 0u;
    for (int p = 3; p >= 0; --p) {
        hist[threadIdx.x] = 0u;
        __syncthreads();
        for (long i = threadIdx.x; i < n; i += blockDim.x) {
            unsigned v = __float_as_uint(data[i]);
            if ((v & pmask) == prefix)
                atomicAdd(&hist[(v >> (p * 8)) & 255u], 1u);
        }
        __syncthreads();
        if (threadIdx.x == 0) {
            long cum = 0, r = s_rank;
            unsigned c = 0;
            for (; c < 256u; ++c) {
                if (cum + (long)hist[c] > r) break;
                cum += (long)hist[c];
            }
            s_sel = c;
            s_rank = r - cum;
        }
        __syncthreads();
        prefix |= (s_sel << (p * 8));
        pmask  |= (0xFFu << (p * 8));
        __syncthreads();
    }
    if (threadIdx.x == 0) ostat[blockIdx.x] = __uint_as_float(prefix);
}

// Median as jnp computes it (linear interpolation): a + 0.5*(b-a), fp32.
__device__ __forceinline__ float med_interp(float a, float b)
{
    return a + 0.5f * (b - a);
}

// ---------------------------------------------------------------------------
// Apply 2x2 tile mask to q and k in place.
// ---------------------------------------------------------------------------
__global__ void mask_qk_k(float* __restrict__ qkv, const float* __restrict__ nq,
                          const float* __restrict__ nk, const float* __restrict__ ostat)
{
    long idx = (long)blockIdx.x * blockDim.x + threadIdx.x;
    if (idx >= 2L * 2097152L) return;
    int tensor = (idx >= 2097152L) ? 1 : 0;
    long t = idx - (long)tensor * 2097152L;
    int b   = (int)(t / (1024 * 512));
    int rem = (int)(t % (1024 * 512));
    int ts  = rem / 512;
    int td  = rem % 512;
    float thr = tensor ? med_interp(ostat[8 + 2 * b], ostat[8 + 2 * b + 1])
                       : med_interp(ostat[2 * b],     ostat[2 * b + 1]);
    float nrm = (tensor ? nk : nq)[t];
    if (nrm < thr) {
        float* p = qkv + (long)b * SS * 3072 + (long)(2 * ts) * 3072
                       + tensor * 1024 + 2 * td;
        p[0] = 0.0f; p[1] = 0.0f; p[3072] = 0.0f; p[3073] = 0.0f;
    }
}

// ---------------------------------------------------------------------------
// Row-masked copy of WO into wom.
// ---------------------------------------------------------------------------
__global__ void mask_wo_k(const float* __restrict__ WO, const float* __restrict__ nw,
                          const float* __restrict__ ostat, float* __restrict__ wom)
{
    long idx = (long)blockIdx.x * blockDim.x + threadIdx.x;   // 8388608
    if (idx >= 8388608L) return;
    long row = idx >> 10;                  // 0..8191
    int  b   = (int)(idx >> 21);           // 2048*1024 per batch
    float thr = med_interp(ostat[16 + 2 * b], ostat[16 + 2 * b + 1]);
    wom[idx] = (nw[row] >= thr) ? WO[idx] : 0.0f;
}

// ---------------------------------------------------------------------------
// Launch: full pipeline, graph-capturable, no allocations.
// Inputs: 0=x (B,S,E) f32, 1=Wqkv (3E,E), 2=bqkv (3E), 3=WO (B,1,S,hd),
//         4=bias (unused by reference). Output: (B,S,E) f32.
// ---------------------------------------------------------------------------
extern "C" void kernel_launch(void* const* d_in, const int* in_sizes, int n_in,
                              void* d_out, int out_size)
{
    const float* x    = (const float*)d_in[0];
    const float* Wqkv = (const float*)d_in[1];
    const float* bqkv = (const float*)d_in[2];
    const float* WO   = (const float*)d_in[3];
    float* out = (float*)d_out;

    float* base = nullptr;
    cudaGetSymbolAddress((void**)&base, g_scratch);
    float* qkv   = base + OFF_QKV;
    float* q1    = base + OFF_Q1;
    float* k1    = base + OFF_K1;
    float* pc    = base + OFF_PC;
    float* sc    = base + OFF_SC;
    float* po    = base + OFF_PO;
    float* wom   = base + OFF_WOM;
    float* nq    = base + OFF_NQ;
    float* nk    = base + OFF_NK;
    float* nw    = base + OFF_NW;
    float* ostat = base + OFF_OST;

    const long sX  = (long)SS * EE;        // 2048*1024
    const long sQK = (long)SS * 3072;      // 2048*3072
    const long sP  = (long)SS * SS;        // 2048*2048

    // 1. qkv = x @ Wqkv^T + bqkv  -- fp64 accumulation, exact to 0.5 ulp.
    gemm_f64acc_k<<<dim3(3072 / 64, 8192 / 64, 1), 256>>>(x, Wqkv, qkv, bqkv);

    // 2. norms (fp64 exact, rounded to fp32 for ranking)
    tile_norm_k<<<(4194304 + 255) / 256, 256>>>(qkv, nq, nk);
    row_norm_k<<<8192, 256>>>(WO, nw);

    // 3. exact medians (both middle order statistics per problem)
    select_k<<<24, 256>>>(nq, nk, nw, ostat);

    // 4. apply masks
    mask_qk_k<<<(4194304 + 255) / 256, 256>>>(qkv, nq, nk, ostat);
    mask_wo_k<<<(8388608 + 255) / 256, 256>>>(WO, nw, ostat, wom);

    // 5. q_ = x @ qm^T     (per batch: 2048x2048x1024)
    gemm_k<true><<<dim3(16, 16, 4), 256>>>(
        x, qkv + 0, q1, 2048, 2048, 1024,
        1024, 3072, 2048, sX, sQK, sP, 1.0f);

    // 6. k_ = x @ km^T
    gemm_k<true><<<dim3(16, 16, 4), 256>>>(
        x, qkv + 1024, k1, 2048, 2048, 1024,
        1024, 3072, 2048, sX, sQK, sP, 1.0f);

    // 7. precompute = v @ wom^T
    gemm_k<true><<<dim3(16, 16, 4), 256>>>(
        qkv + 2048, wom, pc, 2048, 2048, 1024,
        3072, 1024, 2048, sQK, sX, sP, 1.0f);

    // 8. preoutput = precompute @ x   (2048x1024x2048, NN)
    gemm_k<false><<<dim3(8, 16, 4), 256>>>(
        pc, x, po, 2048, 1024, 2048,
        2048, 1024, 1024, sP, sX, sX, 1.0f);

    // 9. scale_values = (q_/32) @ k_^T   (2048x2048x2048, NT, alpha=1/32 exact)
    gemm_k<true><<<dim3(16, 16, 4), 256>>>(
        q1, k1, sc, 2048, 2048, 2048,
        2048, 2048, 2048, sP, sP, sP, 0.03125f);

    // 10. output = scale_values @ preoutput   (2048x1024x2048, NN) -> d_out
    gemm_k<false><<<dim3(8, 16, 4), 256>>>(
        sc, po, out, 2048, 1024, 2048,
        2048, 1024, 1024, sP, sX, sX, 1.0f);
}

// round 6
// speedup vs baseline: 1.0439x; 1.0439x over previous
#include <cuda_runtime.h>

// ---------------------------------------------------------------------------
// Problem constants: B=4, S=2048, E=1024, H=1, hd=1024
//
// Numerics strategy (reference is pure fp32 JAX/XLA, unknown reduction order):
//   - Mask path (qkv GEMM, norms, median) in fp64, rounded once to fp32.
//   - Downstream GEMMs plain fp32 (headroom is thin: rel_err 7e-4 of 1e-3
//     comes from one reference-side knife-edge tile; keep our side exact-ish).
// ---------------------------------------------------------------------------
#define BB 4
#define SS 2048
#define EE 1024

#define OFF_QKV   0L                          // 4*2048*3072 = 25165824
#define OFF_Q1    (OFF_QKV + 25165824L)       // q_  4*2048*2048 = 16777216
#define OFF_K1    (OFF_Q1  + 16777216L)       // k_
#define OFF_PC    (OFF_K1  + 16777216L)       // precompute
#define OFF_SC    (OFF_PC  + 16777216L)       // scale_values
#define OFF_PO    (OFF_SC  + 16777216L)       // preoutput 4*2048*1024 = 8388608
#define OFF_WOM   (OFF_PO  + 8388608L)        // masked WO 8388608
#define OFF_NQ    (OFF_WOM + 8388608L)        // tile norms q 4*1024*512 = 2097152
#define OFF_NK    (OFF_NQ  + 2097152L)        // tile norms k
#define OFF_NW    (OFF_NK  + 2097152L)        // row norms WO 4*2048 = 8192
#define OFF_OST   (OFF_NW  + 8192L)           // 24 order statistics
#define SCRATCH_TOTAL (OFF_OST + 32L)

__device__ float g_scratch[SCRATCH_TOTAL];

// Parallel radix-select state.
__device__ unsigned g_hist[24 * 256];
__device__ unsigned g_prefix[24];
__device__ int      g_rankrem[24];

// ---------------------------------------------------------------------------
// qkv GEMM with fp64 accumulation:
// C[m,n] = round_f32( sum_k (double)A[m,k]*(double)B[n,k] + bias )
// A: 8192x1024, B(=Wqkv): 3072x1024 (both row-major), C: 8192x3072.
// ---------------------------------------------------------------------------
__global__ __launch_bounds__(256)
void gemm_f64acc_k(const float* __restrict__ A, const float* __restrict__ B,
                   float* __restrict__ C, const float* __restrict__ bias)
{
    __shared__ float As[16][64];
    __shared__ float Bs[16][64];

    const int tid = threadIdx.x;
    const int bm  = blockIdx.y * 64;
    const int bn  = blockIdx.x * 64;
    const int tx  = tid & 15;
    const int ty  = tid >> 4;
    const int lrow = tid >> 2;
    const int lcol = (tid & 3) * 4;

    double acc[4][4];
#pragma unroll
    for (int i = 0; i < 4; i++)
#pragma unroll
        for (int j = 0; j < 4; j++) acc[i][j] = 0.0;

    for (int k0 = 0; k0 < 1024; k0 += 16) {
        float4 av = *(const float4*)(A + (long)(bm + lrow) * 1024 + k0 + lcol);
        As[lcol + 0][lrow] = av.x;
        As[lcol + 1][lrow] = av.y;
        As[lcol + 2][lrow] = av.z;
        As[lcol + 3][lrow] = av.w;
        float4 bv = *(const float4*)(B + (long)(bn + lrow) * 1024 + k0 + lcol);
        Bs[lcol + 0][lrow] = bv.x;
        Bs[lcol + 1][lrow] = bv.y;
        Bs[lcol + 2][lrow] = bv.z;
        Bs[lcol + 3][lrow] = bv.w;
        __syncthreads();
#pragma unroll
        for (int kk = 0; kk < 16; ++kk) {
            double a[4], b[4];
#pragma unroll
            for (int i = 0; i < 4; i++) a[i] = (double)As[kk][ty * 4 + i];
#pragma unroll
            for (int j = 0; j < 4; j++) b[j] = (double)Bs[kk][tx * 4 + j];
#pragma unroll
            for (int i = 0; i < 4; i++)
#pragma unroll
                for (int j = 0; j < 4; j++)
                    acc[i][j] = fma(a[i], b[j], acc[i][j]);
        }
        __syncthreads();
    }

#pragma unroll
    for (int i = 0; i < 4; i++) {
        float* crow = C + (long)(bm + ty * 4 + i) * 3072 + bn + tx * 4;
#pragma unroll
        for (int j = 0; j < 4; j++)
            crow[j] = (float)(acc[i][j] + (double)bias[bn + tx * 4 + j]);
    }
}

// ---------------------------------------------------------------------------
// Double-buffered fp32 tiled GEMM: C = alpha * A * op(B)
// A: M x K row-major (lda), B: TRANSB ? (N x K, ldb) : (K x N, ldb)
// C: M x N row-major (ldc). Batched via blockIdx.z.
// 128x128 tile, K-panel 8, 256 threads, 8x8 per thread, one sync per panel.
// Per-thread accumulation order identical to round-5 kernel (bit-exact).
// ---------------------------------------------------------------------------
template<bool TRANSB>
__global__ __launch_bounds__(256)
void gemm_k(const float* __restrict__ A, const float* __restrict__ B,
            float* __restrict__ C,
            int M, int N, int K, int lda, int ldb, int ldc,
            long sA, long sB, long sC, float alpha)
{
    const int bz = blockIdx.z;
    A += (long)bz * sA;
    B += (long)bz * sB;
    C += (long)bz * sC;

    __shared__ float As[2][8][128];
    __shared__ float Bs[2][8][128];

    const int tid  = threadIdx.x;
    const int bm   = blockIdx.y * 128;
    const int bn   = blockIdx.x * 128;
    const int tx   = tid & 15;
    const int ty   = tid >> 4;
    const int arow = tid >> 1;
    const int acol = (tid & 1) * 4;
    const int brow = tid >> 5;
    const int bcol = (tid & 31) * 4;

    const float* Ap  = A + (long)(bm + arow) * lda + acol;
    const float* BpT = B + (long)(bn + arow) * ldb + acol;
    const float* BpN = B + (long)brow * ldb + bn + bcol;

    float acc[8][8];
#pragma unroll
    for (int i = 0; i < 8; i++)
#pragma unroll
        for (int j = 0; j < 8; j++) acc[i][j] = 0.0f;

    // Prologue: panel 0 into buffer 0.
    {
        float4 av = *(const float4*)Ap;
        As[0][acol + 0][arow] = av.x;
        As[0][acol + 1][arow] = av.y;
        As[0][acol + 2][arow] = av.z;
        As[0][acol + 3][arow] = av.w;
        if (TRANSB) {
            float4 bv = *(const float4*)BpT;
            Bs[0][acol + 0][arow] = bv.x;
            Bs[0][acol + 1][arow] = bv.y;
            Bs[0][acol + 2][arow] = bv.z;
            Bs[0][acol + 3][arow] = bv.w;
        } else {
            *(float4*)&Bs[0][brow][bcol] = *(const float4*)BpN;
        }
    }
    __syncthreads();

    const int nP = K >> 3;
    for (int p = 0; p < nP; ++p) {
        float4 av2, bv2;
        const bool more = (p + 1 < nP);
        if (more) {
            av2 = *(const float4*)(Ap + (p + 1) * 8);
            bv2 = TRANSB ? *(const float4*)(BpT + (p + 1) * 8)
                         : *(const float4*)(BpN + (long)(p + 1) * 8 * ldb);
        }
        const int cb = p & 1;
#pragma unroll
        for (int kk = 0; kk < 8; ++kk) {
            float4 a0 = *(const float4*)&As[cb][kk][ty * 8];
            float4 a1 = *(const float4*)&As[cb][kk][ty * 8 + 4];
            float4 b0 = *(const float4*)&Bs[cb][kk][tx * 8];
            float4 b1 = *(const float4*)&Bs[cb][kk][tx * 8 + 4];
            float a[8] = {a0.x, a0.y, a0.z, a0.w, a1.x, a1.y, a1.z, a1.w};
            float b[8] = {b0.x, b0.y, b0.z, b0.w, b1.x, b1.y, b1.z, b1.w};
#pragma unroll
            for (int i = 0; i < 8; i++)
#pragma unroll
                for (int j = 0; j < 8; j++)
                    acc[i][j] = fmaf(a[i], b[j], acc[i][j]);
        }
        if (more) {
            const int nb = cb ^ 1;
            As[nb][acol + 0][arow] = av2.x;
            As[nb][acol + 1][arow] = av2.y;
            As[nb][acol + 2][arow] = av2.z;
            As[nb][acol + 3][arow] = av2.w;
            if (TRANSB) {
                Bs[nb][acol + 0][arow] = bv2.x;
                Bs[nb][acol + 1][arow] = bv2.y;
                Bs[nb][acol + 2][arow] = bv2.z;
                Bs[nb][acol + 3][arow] = bv2.w;
            } else {
                *(float4*)&Bs[nb][brow][bcol] = bv2;
            }
            __syncthreads();
        }
    }

#pragma unroll
    for (int i = 0; i < 8; i++) {
        float* crow = C + (long)(bm + ty * 8 + i) * ldc + bn + tx * 8;
#pragma unroll
        for (int j = 0; j < 8; j++)
            crow[j] = acc[i][j] * alpha;
    }
}

// ---------------------------------------------------------------------------
// Tile norms for q and k (fp64, rounded once to fp32).
// ---------------------------------------------------------------------------
__global__ void tile_norm_k(const float* __restrict__ qkv,
                            float* __restrict__ nq, float* __restrict__ nk)
{
    long idx = (long)blockIdx.x * blockDim.x + threadIdx.x;
    if (idx >= 2L * 2097152L) return;
    int tensor = (idx >= 2097152L) ? 1 : 0;
    long t = idx - (long)tensor * 2097152L;
    int b   = (int)(t / (1024 * 512));
    int rem = (int)(t % (1024 * 512));
    int ts  = rem / 512;
    int td  = rem % 512;
    const float* p = qkv + (long)b * SS * 3072 + (long)(2 * ts) * 3072
                         + tensor * 1024 + 2 * td;
    double v00 = p[0], v01 = p[1], v10 = p[3072], v11 = p[3073];
    double n = sqrt(v00 * v00 + v01 * v01 + v10 * v10 + v11 * v11);
    (tensor ? nk : nq)[t] = (float)n;
}

// ---------------------------------------------------------------------------
// Row norms of WO (fp64): one block per row.
// ---------------------------------------------------------------------------
__global__ void row_norm_k(const float* __restrict__ WO, float* __restrict__ nw)
{
    int row = blockIdx.x;
    const float* p = WO + (long)row * 1024;
    double s = 0.0;
    for (int i = threadIdx.x; i < 1024; i += 256) {
        double v = p[i];
        s += v * v;
    }
    __shared__ double red[256];
    red[threadIdx.x] = s;
    __syncthreads();
    for (int off = 128; off > 0; off >>= 1) {
        if (threadIdx.x < off) red[threadIdx.x] += red[threadIdx.x + off];
        __syncthreads();
    }
    if (threadIdx.x == 0) nw[row] = (float)sqrt(red[0]);
}

// ---------------------------------------------------------------------------
// Parallel exact order statistic: MSB-first byte radix select over 24 targets.
// target t: pid = t>>1 (0..3 nq batches, 4..7 nk, 8..11 nw), which = t&1.
// Same selection semantics as the round-5 single-block version (bit-exact).
// ---------------------------------------------------------------------------
__global__ void sel_init_k()
{
    int t = blockIdx.x;               // 0..23
    g_hist[t * 256 + threadIdx.x] = 0u;
    if (threadIdx.x == 0) {
        g_prefix[t]  = 0u;
        g_rankrem[t] = (t < 16) ? (262143 + (t & 1)) : (1023 + (t & 1));
    }
}

__global__ void sel_hist_k(int level, const float* __restrict__ nq,
                           const float* __restrict__ nk,
                           const float* __restrict__ nw)
{
    const int t   = blockIdx.y;
    const int pid = t >> 1;
    const float* data;
    int n;
    if (pid < 4)      { data = nq + (long)pid * 524288L;       n = 524288; }
    else if (pid < 8) { data = nk + (long)(pid - 4) * 524288L; n = 524288; }
    else              { data = nw + (long)(pid - 8) * 2048L;   n = 2048;   }

    __shared__ unsigned h[256];
    h[threadIdx.x] = 0u;
    __syncthreads();

    const unsigned prefix = g_prefix[t];
    const unsigned pmask  = (level == 3) ? 0u : (0xFFFFFFFFu << ((level + 1) * 8));
    const int sh = level * 8;

    for (int i = blockIdx.x * 256 + threadIdx.x; i < n; i += gridDim.x * 256) {
        unsigned v = __float_as_uint(data[i]);
        if ((v & pmask) == prefix)
            atomicAdd(&h[(v >> sh) & 255u], 1u);
    }
    __syncthreads();
    unsigned c = h[threadIdx.x];
    if (c) atomicAdd(&g_hist[t * 256 + threadIdx.x], c);
}

__global__ void sel_pick_k(int level, float* __restrict__ ostat)
{
    const int t = blockIdx.x;
    __shared__ unsigned h[256];
    h[threadIdx.x] = g_hist[t * 256 + threadIdx.x];
    g_hist[t * 256 + threadIdx.x] = 0u;          // ready for next level
    __syncthreads();
    if (threadIdx.x == 0) {
        int r = g_rankrem[t];
        long cum = 0;
        unsigned c = 0;
        for (; c < 256u; ++c) {
            if (cum + (long)h[c] > (long)r) break;
            cum += (long)h[c];
        }
        unsigned pfx = g_prefix[t] | (c << (level * 8));
        g_prefix[t]  = pfx;
        g_rankrem[t] = r - (int)cum;
        if (level == 0) ostat[t] = __uint_as_float(pfx);
    }
}

// Median as jnp computes it: a + 0.5*(b-a), fp32.
__device__ __forceinline__ float med_interp(float a, float b)
{
    return a + 0.5f * (b - a);
}

// ---------------------------------------------------------------------------
// Apply 2x2 tile mask to q and k in place.
// ---------------------------------------------------------------------------
__global__ void mask_qk_k(float* __restrict__ qkv, const float* __restrict__ nq,
                          const float* __restrict__ nk, const float* __restrict__ ostat)
{
    long idx = (long)blockIdx.x * blockDim.x + threadIdx.x;
    if (idx >= 2L * 2097152L) return;
    int tensor = (idx >= 2097152L) ? 1 : 0;
    long t = idx - (long)tensor * 2097152L;
    int b   = (int)(t / (1024 * 512));
    int rem = (int)(t % (1024 * 512));
    int ts  = rem / 512;
    int td  = rem % 512;
    float thr = tensor ? med_interp(ostat[8 + 2 * b], ostat[8 + 2 * b + 1])
                       : med_interp(ostat[2 * b],     ostat[2 * b + 1]);
    float nrm = (tensor ? nk : nq)[t];
    if (nrm < thr) {
        float* p = qkv + (long)b * SS * 3072 + (long)(2 * ts) * 3072
                       + tensor * 1024 + 2 * td;
        p[0] = 0.0f; p[1] = 0.0f; p[3072] = 0.0f; p[3073] = 0.0f;
    }
}

// ---------------------------------------------------------------------------
// Row-masked copy of WO into wom.
// ---------------------------------------------------------------------------
__global__ void mask_wo_k(const float* __restrict__ WO, const float* __restrict__ nw,
                          const float* __restrict__ ostat, float* __restrict__ wom)
{
    long idx = (long)blockIdx.x * blockDim.x + threadIdx.x;
    if (idx >= 8388608L) return;
    long row = idx >> 10;
    int  b   = (int)(idx >> 21);
    float thr = med_interp(ostat[16 + 2 * b], ostat[16 + 2 * b + 1]);
    wom[idx] = (nw[row] >= thr) ? WO[idx] : 0.0f;
}

// ---------------------------------------------------------------------------
// Launch: full pipeline, graph-capturable, no allocations.
// ---------------------------------------------------------------------------
extern "C" void kernel_launch(void* const* d_in, const int* in_sizes, int n_in,
                              void* d_out, int out_size)
{
    const float* x    = (const float*)d_in[0];
    const float* Wqkv = (const float*)d_in[1];
    const float* bqkv = (const float*)d_in[2];
    const float* WO   = (const float*)d_in[3];
    float* out = (float*)d_out;

    float* base = nullptr;
    cudaGetSymbolAddress((void**)&base, g_scratch);
    float* qkv   = base + OFF_QKV;
    float* q1    = base + OFF_Q1;
    float* k1    = base + OFF_K1;
    float* pc    = base + OFF_PC;
    float* sc    = base + OFF_SC;
    float* po    = base + OFF_PO;
    float* wom   = base + OFF_WOM;
    float* nq    = base + OFF_NQ;
    float* nk    = base + OFF_NK;
    float* nw    = base + OFF_NW;
    float* ostat = base + OFF_OST;

    const long sX  = (long)SS * EE;
    const long sQK = (long)SS * 3072;
    const long sP  = (long)SS * SS;

    // 1. qkv = x @ Wqkv^T + bqkv  (fp64 accumulation)
    gemm_f64acc_k<<<dim3(3072 / 64, 8192 / 64, 1), 256>>>(x, Wqkv, qkv, bqkv);

    // 2. norms
    tile_norm_k<<<(4194304 + 255) / 256, 256>>>(qkv, nq, nk);
    row_norm_k<<<8192, 256>>>(WO, nw);

    // 3. exact medians — parallel radix select, 4 byte levels MSB->LSB.
    sel_init_k<<<24, 256>>>();
    for (int level = 3; level >= 0; --level) {
        sel_hist_k<<<dim3(48, 24), 256>>>(level, nq, nk, nw);
        sel_pick_k<<<24, 256>>>(level, ostat);
    }

    // 4. apply masks
    mask_qk_k<<<(4194304 + 255) / 256, 256>>>(qkv, nq, nk, ostat);
    mask_wo_k<<<(8388608 + 255) / 256, 256>>>(WO, nw, ostat, wom);

    // 5. q_ = x @ qm^T     (per batch: 2048x2048x1024)
    gemm_k<true><<<dim3(16, 16, 4), 256>>>(
        x, qkv + 0, q1, 2048, 2048, 1024,
        1024, 3072, 2048, sX, sQK, sP, 1.0f);

    // 6. k_ = x @ km^T
    gemm_k<true><<<dim3(16, 16, 4), 256>>>(
        x, qkv + 1024, k1, 2048, 2048, 1024,
        1024, 3072, 2048, sX, sQK, sP, 1.0f);

    // 7. precompute = v @ wom^T
    gemm_k<true><<<dim3(16, 16, 4), 256>>>(
        qkv + 2048, wom, pc, 2048, 2048, 1024,
        3072, 1024, 2048, sQK, sX, sP, 1.0f);

    // 8. preoutput = precompute @ x   (2048x1024x2048, NN)
    gemm_k<false><<<dim3(8, 16, 4), 256>>>(
        pc, x, po, 2048, 1024, 2048,
        2048, 1024, 1024, sP, sX, sX, 1.0f);

    // 9. scale_values = (q_/32) @ k_^T (2048x2048x2048, NT, alpha=1/32 exact)
    gemm_k<true><<<dim3(16, 16, 4), 256>>>(
        q1, k1, sc, 2048, 2048, 2048,
        2048, 2048, 2048, sP, sP, sP, 0.03125f);

    // 10. output = scale_values @ preoutput (2048x1024x2048, NN) -> d_out
    gemm_k<false><<<dim3(8, 16, 4), 256>>>(
        sc, po, out, 2048, 1024, 2048,
        2048, 1024, 1024, sP, sX, sX, 1.0f);
}

// round 7
// speedup vs baseline: 1.0898x; 1.0440x over previous
#include <cuda_runtime.h>

// ---------------------------------------------------------------------------
// Problem constants: B=4, S=2048, E=1024, H=1, hd=1024
//
// Numerics:
//   - Mask path (qkv GEMM, norms, median) in fp64, rounded once to fp32.
//     UNCHANGED from the passing round-6 kernel (rel_err floor 7.02e-4 is a
//     reference-side knife-edge tile; our mask path is exact).
//   - Downstream GEMMs: TF32 3-split tensor-core (hi*hi + hi*lo + lo*hi),
//     fp32 accumulate. Error ~2e-7 relative — numerically equivalent to the
//     previous fp32 FMA chain, but on the tensor pipe.
// ---------------------------------------------------------------------------
#define BB 4
#define SS 2048
#define EE 1024

#define OFF_QKV   0L                          // 4*2048*3072
#define OFF_Q1    (OFF_QKV + 25165824L)
#define OFF_K1    (OFF_Q1  + 16777216L)
#define OFF_PC    (OFF_K1  + 16777216L)
#define OFF_SC    (OFF_PC  + 16777216L)
#define OFF_PO    (OFF_SC  + 16777216L)
#define OFF_WOM   (OFF_PO  + 8388608L)
#define OFF_NQ    (OFF_WOM + 8388608L)
#define OFF_NK    (OFF_NQ  + 2097152L)
#define OFF_NW    (OFF_NK  + 2097152L)
#define OFF_OST   (OFF_NW  + 8192L)
#define SCRATCH_TOTAL (OFF_OST + 32L)

__device__ float g_scratch[SCRATCH_TOTAL];

// Parallel radix-select state.
__device__ unsigned g_hist[24 * 256];
__device__ unsigned g_prefix[24];
__device__ int      g_rankrem[24];

// ---------------------------------------------------------------------------
// fp64-accumulation qkv GEMM (mask path; unchanged from round 6).
// ---------------------------------------------------------------------------
__global__ __launch_bounds__(256)
void gemm_f64acc_k(const float* __restrict__ A, const float* __restrict__ B,
                   float* __restrict__ C, const float* __restrict__ bias)
{
    __shared__ float As[16][64];
    __shared__ float Bs[16][64];

    const int tid = threadIdx.x;
    const int bm  = blockIdx.y * 64;
    const int bn  = blockIdx.x * 64;
    const int tx  = tid & 15;
    const int ty  = tid >> 4;
    const int lrow = tid >> 2;
    const int lcol = (tid & 3) * 4;

    double acc[4][4];
#pragma unroll
    for (int i = 0; i < 4; i++)
#pragma unroll
        for (int j = 0; j < 4; j++) acc[i][j] = 0.0;

    for (int k0 = 0; k0 < 1024; k0 += 16) {
        float4 av = *(const float4*)(A + (long)(bm + lrow) * 1024 + k0 + lcol);
        As[lcol + 0][lrow] = av.x;
        As[lcol + 1][lrow] = av.y;
        As[lcol + 2][lrow] = av.z;
        As[lcol + 3][lrow] = av.w;
        float4 bv = *(const float4*)(B + (long)(bn + lrow) * 1024 + k0 + lcol);
        Bs[lcol + 0][lrow] = bv.x;
        Bs[lcol + 1][lrow] = bv.y;
        Bs[lcol + 2][lrow] = bv.z;
        Bs[lcol + 3][lrow] = bv.w;
        __syncthreads();
#pragma unroll
        for (int kk = 0; kk < 16; ++kk) {
            double a[4], b[4];
#pragma unroll
            for (int i = 0; i < 4; i++) a[i] = (double)As[kk][ty * 4 + i];
#pragma unroll
            for (int j = 0; j < 4; j++) b[j] = (double)Bs[kk][tx * 4 + j];
#pragma unroll
            for (int i = 0; i < 4; i++)
#pragma unroll
                for (int j = 0; j < 4; j++)
                    acc[i][j] = fma(a[i], b[j], acc[i][j]);
        }
        __syncthreads();
    }

#pragma unroll
    for (int i = 0; i < 4; i++) {
        float* crow = C + (long)(bm + ty * 4 + i) * 3072 + bn + tx * 4;
#pragma unroll
        for (int j = 0; j < 4; j++)
            crow[j] = (float)(acc[i][j] + (double)bias[bn + tx * 4 + j]);
    }
}

// ---------------------------------------------------------------------------
// TF32 helpers.
// ---------------------------------------------------------------------------
__device__ __forceinline__ float tf32r(float x)
{
    unsigned u;
    asm("cvt.rna.tf32.f32 %0, %1;" : "=r"(u) : "f"(x));
    return __uint_as_float(u);
}

__device__ __forceinline__ void mma1688(float* d, const unsigned* a, const unsigned* b)
{
    asm volatile(
        "mma.sync.aligned.m16n8k8.row.col.f32.tf32.tf32.f32 "
        "{%0,%1,%2,%3}, {%4,%5,%6,%7}, {%8,%9}, {%0,%1,%2,%3};"
        : "+f"(d[0]), "+f"(d[1]), "+f"(d[2]), "+f"(d[3])
        : "r"(a[0]), "r"(a[1]), "r"(a[2]), "r"(a[3]), "r"(b[0]), "r"(b[1]));
}

// ---------------------------------------------------------------------------
// TF32 3-split tensor-core GEMM: C = alpha * A * op(B)
// A: M x K row-major (lda), B: TRANSB ? (N x K, ldb) : (K x N, ldb)
// C: M x N row-major (ldc). Batched via blockIdx.z.
// Block tile 128x128, 8 warps (2 M x 4 N), warp tile 64x32, K-panel 16.
// Each fp32 operand is split error-free into hi+lo tf32; accumulate
// hi*hi + hi*lo + lo*hi in fp32 (dropped lo*lo ~2^-22 relative).
// M, N multiples of 128; K multiple of 16.
// ---------------------------------------------------------------------------
template<bool TRANSB>
__global__ __launch_bounds__(256)
void gemm_tc(const float* __restrict__ A, const float* __restrict__ B,
             float* __restrict__ C,
             int M, int N, int K, int lda, int ldb, int ldc,
             long sA, long sB, long sC, float alpha)
{
    const int bz = blockIdx.z;
    A += (long)bz * sA;
    B += (long)bz * sB;
    C += (long)bz * sC;

    __shared__ float Ah[16][132], Al[16][132];
    __shared__ float Bh[16][132], Bl[16][132];

    const int tid  = threadIdx.x;
    const int lane = tid & 31;
    const int warp = tid >> 5;
    const int wm   = (warp & 1) * 64;     // warp M offset in tile
    const int wn   = (warp >> 1) * 32;    // warp N offset in tile
    const int gid  = lane >> 2;           // 0..7
    const int tig  = lane & 3;            // 0..3
    const int bm   = blockIdx.y * 128;
    const int bn   = blockIdx.x * 128;

    float acc[4][4][4];
#pragma unroll
    for (int mt = 0; mt < 4; mt++)
#pragma unroll
        for (int nt = 0; nt < 4; nt++)
#pragma unroll
            for (int r = 0; r < 4; r++) acc[mt][nt][r] = 0.0f;

    for (int k0 = 0; k0 < K; k0 += 16) {
        // --- load + split A panel (128 rows x 16 k) ---
#pragma unroll
        for (int rep = 0; rep < 2; rep++) {
            int slot = tid + rep * 256;            // 0..511 float4 slots
            int row  = slot >> 2;                  // 0..127
            int kc   = (slot & 3) * 4;             // 0,4,8,12
            float4 v = *(const float4*)(A + (long)(bm + row) * lda + k0 + kc);
            float f[4] = {v.x, v.y, v.z, v.w};
#pragma unroll
            for (int i = 0; i < 4; i++) {
                float hi = tf32r(f[i]);
                Ah[kc + i][row] = hi;
                Al[kc + i][row] = tf32r(f[i] - hi);
            }
        }
        // --- load + split B panel into [k][n] layout ---
#pragma unroll
        for (int rep = 0; rep < 2; rep++) {
            int slot = tid + rep * 256;
            if (TRANSB) {
                int row = slot >> 2;               // n index 0..127
                int kc  = (slot & 3) * 4;
                float4 v = *(const float4*)(B + (long)(bn + row) * ldb + k0 + kc);
                float f[4] = {v.x, v.y, v.z, v.w};
#pragma unroll
                for (int i = 0; i < 4; i++) {
                    float hi = tf32r(f[i]);
                    Bh[kc + i][row] = hi;
                    Bl[kc + i][row] = tf32r(f[i] - hi);
                }
            } else {
                int krow = slot >> 5;              // 0..15
                int nc   = (slot & 31) * 4;        // 0..124
                float4 v = *(const float4*)(B + (long)(k0 + krow) * ldb + bn + nc);
                float f[4] = {v.x, v.y, v.z, v.w};
#pragma unroll
                for (int i = 0; i < 4; i++) {
                    float hi = tf32r(f[i]);
                    Bh[krow][nc + i] = hi;
                    Bl[krow][nc + i] = tf32r(f[i] - hi);
                }
            }
        }
        __syncthreads();

        // --- two k8 MMA steps ---
#pragma unroll
        for (int ks = 0; ks < 16; ks += 8) {
            unsigned ah[4][4], al[4][4];
#pragma unroll
            for (int mt = 0; mt < 4; mt++) {
                int m0 = wm + mt * 16;
                ah[mt][0] = __float_as_uint(Ah[ks + tig][m0 + gid]);
                ah[mt][1] = __float_as_uint(Ah[ks + tig][m0 + 8 + gid]);
                ah[mt][2] = __float_as_uint(Ah[ks + tig + 4][m0 + gid]);
                ah[mt][3] = __float_as_uint(Ah[ks + tig + 4][m0 + 8 + gid]);
                al[mt][0] = __float_as_uint(Al[ks + tig][m0 + gid]);
                al[mt][1] = __float_as_uint(Al[ks + tig][m0 + 8 + gid]);
                al[mt][2] = __float_as_uint(Al[ks + tig + 4][m0 + gid]);
                al[mt][3] = __float_as_uint(Al[ks + tig + 4][m0 + 8 + gid]);
            }
#pragma unroll
            for (int nt = 0; nt < 4; nt++) {
                int n0 = wn + nt * 8;
                unsigned bh[2], bl[2];
                bh[0] = __float_as_uint(Bh[ks + tig][n0 + gid]);
                bh[1] = __float_as_uint(Bh[ks + tig + 4][n0 + gid]);
                bl[0] = __float_as_uint(Bl[ks + tig][n0 + gid]);
                bl[1] = __float_as_uint(Bl[ks + tig + 4][n0 + gid]);
#pragma unroll
                for (int mt = 0; mt < 4; mt++) {
                    mma1688(acc[mt][nt], ah[mt], bh);   // hi*hi
                    mma1688(acc[mt][nt], ah[mt], bl);   // hi*lo
                    mma1688(acc[mt][nt], al[mt], bh);   // lo*hi
                }
            }
        }
        __syncthreads();
    }

    // --- epilogue: c0,c1 at (row, 2*tig), (row, 2*tig+1); c2,c3 at row+8 ---
#pragma unroll
    for (int mt = 0; mt < 4; mt++) {
#pragma unroll
        for (int nt = 0; nt < 4; nt++) {
            int row = bm + wm + mt * 16 + gid;
            int col = bn + wn + nt * 8 + 2 * tig;
            float2 v0 = {acc[mt][nt][0] * alpha, acc[mt][nt][1] * alpha};
            float2 v1 = {acc[mt][nt][2] * alpha, acc[mt][nt][3] * alpha};
            *(float2*)(C + (long)row * ldc + col)       = v0;
            *(float2*)(C + (long)(row + 8) * ldc + col) = v1;
        }
    }
}

// ---------------------------------------------------------------------------
// Tile norms for q and k (fp64, rounded once to fp32).
// ---------------------------------------------------------------------------
__global__ void tile_norm_k(const float* __restrict__ qkv,
                            float* __restrict__ nq, float* __restrict__ nk)
{
    long idx = (long)blockIdx.x * blockDim.x + threadIdx.x;
    if (idx >= 2L * 2097152L) return;
    int tensor = (idx >= 2097152L) ? 1 : 0;
    long t = idx - (long)tensor * 2097152L;
    int b   = (int)(t / (1024 * 512));
    int rem = (int)(t % (1024 * 512));
    int ts  = rem / 512;
    int td  = rem % 512;
    const float* p = qkv + (long)b * SS * 3072 + (long)(2 * ts) * 3072
                         + tensor * 1024 + 2 * td;
    double v00 = p[0], v01 = p[1], v10 = p[3072], v11 = p[3073];
    double n = sqrt(v00 * v00 + v01 * v01 + v10 * v10 + v11 * v11);
    (tensor ? nk : nq)[t] = (float)n;
}

// ---------------------------------------------------------------------------
// Row norms of WO (fp64): one block per row.
// ---------------------------------------------------------------------------
__global__ void row_norm_k(const float* __restrict__ WO, float* __restrict__ nw)
{
    int row = blockIdx.x;
    const float* p = WO + (long)row * 1024;
    double s = 0.0;
    for (int i = threadIdx.x; i < 1024; i += 256) {
        double v = p[i];
        s += v * v;
    }
    __shared__ double red[256];
    red[threadIdx.x] = s;
    __syncthreads();
    for (int off = 128; off > 0; off >>= 1) {
        if (threadIdx.x < off) red[threadIdx.x] += red[threadIdx.x + off];
        __syncthreads();
    }
    if (threadIdx.x == 0) nw[row] = (float)sqrt(red[0]);
}

// ---------------------------------------------------------------------------
// Parallel exact order statistic (unchanged from round 6).
// ---------------------------------------------------------------------------
__global__ void sel_init_k()
{
    int t = blockIdx.x;
    g_hist[t * 256 + threadIdx.x] = 0u;
    if (threadIdx.x == 0) {
        g_prefix[t]  = 0u;
        g_rankrem[t] = (t < 16) ? (262143 + (t & 1)) : (1023 + (t & 1));
    }
}

__global__ void sel_hist_k(int level, const float* __restrict__ nq,
                           const float* __restrict__ nk,
                           const float* __restrict__ nw)
{
    const int t   = blockIdx.y;
    const int pid = t >> 1;
    const float* data;
    int n;
    if (pid < 4)      { data = nq + (long)pid * 524288L;       n = 524288; }
    else if (pid < 8) { data = nk + (long)(pid - 4) * 524288L; n = 524288; }
    else              { data = nw + (long)(pid - 8) * 2048L;   n = 2048;   }

    __shared__ unsigned h[256];
    h[threadIdx.x] = 0u;
    __syncthreads();

    const unsigned prefix = g_prefix[t];
    const unsigned pmask  = (level == 3) ? 0u : (0xFFFFFFFFu << ((level + 1) * 8));
    const int sh = level * 8;

    for (int i = blockIdx.x * 256 + threadIdx.x; i < n; i += gridDim.x * 256) {
        unsigned v = __float_as_uint(data[i]);
        if ((v & pmask) == prefix)
            atomicAdd(&h[(v >> sh) & 255u], 1u);
    }
    __syncthreads();
    unsigned c = h[threadIdx.x];
    if (c) atomicAdd(&g_hist[t * 256 + threadIdx.x], c);
}

__global__ void sel_pick_k(int level, float* __restrict__ ostat)
{
    const int t = blockIdx.x;
    __shared__ unsigned h[256];
    h[threadIdx.x] = g_hist[t * 256 + threadIdx.x];
    g_hist[t * 256 + threadIdx.x] = 0u;
    __syncthreads();
    if (threadIdx.x == 0) {
        int r = g_rankrem[t];
        long cum = 0;
        unsigned c = 0;
        for (; c < 256u; ++c) {
            if (cum + (long)h[c] > (long)r) break;
            cum += (long)h[c];
        }
        unsigned pfx = g_prefix[t] | (c << (level * 8));
        g_prefix[t]  = pfx;
        g_rankrem[t] = r - (int)cum;
        if (level == 0) ostat[t] = __uint_as_float(pfx);
    }
}

__device__ __forceinline__ float med_interp(float a, float b)
{
    return a + 0.5f * (b - a);
}

// ---------------------------------------------------------------------------
// Apply 2x2 tile mask to q and k in place.
// ---------------------------------------------------------------------------
__global__ void mask_qk_k(float* __restrict__ qkv, const float* __restrict__ nq,
                          const float* __restrict__ nk, const float* __restrict__ ostat)
{
    long idx = (long)blockIdx.x * blockDim.x + threadIdx.x;
    if (idx >= 2L * 2097152L) return;
    int tensor = (idx >= 2097152L) ? 1 : 0;
    long t = idx - (long)tensor * 2097152L;
    int b   = (int)(t / (1024 * 512));
    int rem = (int)(t % (1024 * 512));
    int ts  = rem / 512;
    int td  = rem % 512;
    float thr = tensor ? med_interp(ostat[8 + 2 * b], ostat[8 + 2 * b + 1])
                       : med_interp(ostat[2 * b],     ostat[2 * b + 1]);
    float nrm = (tensor ? nk : nq)[t];
    if (nrm < thr) {
        float* p = qkv + (long)b * SS * 3072 + (long)(2 * ts) * 3072
                       + tensor * 1024 + 2 * td;
        p[0] = 0.0f; p[1] = 0.0f; p[3072] = 0.0f; p[3073] = 0.0f;
    }
}

// ---------------------------------------------------------------------------
// Row-masked copy of WO into wom.
// ---------------------------------------------------------------------------
__global__ void mask_wo_k(const float* __restrict__ WO, const float* __restrict__ nw,
                          const float* __restrict__ ostat, float* __restrict__ wom)
{
    long idx = (long)blockIdx.x * blockDim.x + threadIdx.x;
    if (idx >= 8388608L) return;
    long row = idx >> 10;
    int  b   = (int)(idx >> 21);
    float thr = med_interp(ostat[16 + 2 * b], ostat[16 + 2 * b + 1]);
    wom[idx] = (nw[row] >= thr) ? WO[idx] : 0.0f;
}

// ---------------------------------------------------------------------------
// Launch: full pipeline, graph-capturable, no allocations.
// ---------------------------------------------------------------------------
extern "C" void kernel_launch(void* const* d_in, const int* in_sizes, int n_in,
                              void* d_out, int out_size)
{
    const float* x    = (const float*)d_in[0];
    const float* Wqkv = (const float*)d_in[1];
    const float* bqkv = (const float*)d_in[2];
    const float* WO   = (const float*)d_in[3];
    float* out = (float*)d_out;

    float* base = nullptr;
    cudaGetSymbolAddress((void**)&base, g_scratch);
    float* qkv   = base + OFF_QKV;
    float* q1    = base + OFF_Q1;
    float* k1    = base + OFF_K1;
    float* pc    = base + OFF_PC;
    float* sc    = base + OFF_SC;
    float* po    = base + OFF_PO;
    float* wom   = base + OFF_WOM;
    float* nq    = base + OFF_NQ;
    float* nk    = base + OFF_NK;
    float* nw    = base + OFF_NW;
    float* ostat = base + OFF_OST;

    const long sX  = (long)SS * EE;
    const long sQK = (long)SS * 3072;
    const long sP  = (long)SS * SS;

    // 1. qkv = x @ Wqkv^T + bqkv  (fp64 accumulation; mask path)
    gemm_f64acc_k<<<dim3(3072 / 64, 8192 / 64, 1), 256>>>(x, Wqkv, qkv, bqkv);

    // 2. norms
    tile_norm_k<<<(4194304 + 255) / 256, 256>>>(qkv, nq, nk);
    row_norm_k<<<8192, 256>>>(WO, nw);

    // 3. exact medians — parallel radix select.
    sel_init_k<<<24, 256>>>();
    for (int level = 3; level >= 0; --level) {
        sel_hist_k<<<dim3(48, 24), 256>>>(level, nq, nk, nw);
        sel_pick_k<<<24, 256>>>(level, ostat);
    }

    // 4. apply masks
    mask_qk_k<<<(4194304 + 255) / 256, 256>>>(qkv, nq, nk, ostat);
    mask_wo_k<<<(8388608 + 255) / 256, 256>>>(WO, nw, ostat, wom);

    // 5. q_ = x @ qm^T     (2048x2048x1024 per batch, NT)
    gemm_tc<true><<<dim3(16, 16, 4), 256>>>(
        x, qkv + 0, q1, 2048, 2048, 1024,
        1024, 3072, 2048, sX, sQK, sP, 1.0f);

    // 6. k_ = x @ km^T
    gemm_tc<true><<<dim3(16, 16, 4), 256>>>(
        x, qkv + 1024, k1, 2048, 2048, 1024,
        1024, 3072, 2048, sX, sQK, sP, 1.0f);

    // 7. precompute = v @ wom^T
    gemm_tc<true><<<dim3(16, 16, 4), 256>>>(
        qkv + 2048, wom, pc, 2048, 2048, 1024,
        3072, 1024, 2048, sQK, sX, sP, 1.0f);

    // 8. preoutput = precompute @ x   (2048x1024x2048, NN)
    gemm_tc<false><<<dim3(8, 16, 4), 256>>>(
        pc, x, po, 2048, 1024, 2048,
        2048, 1024, 1024, sP, sX, sX, 1.0f);

    // 9. scale_values = (q_/32) @ k_^T (2048x2048x2048, NT, alpha=1/32 exact)
    gemm_tc<true><<<dim3(16, 16, 4), 256>>>(
        q1, k1, sc, 2048, 2048, 2048,
        2048, 2048, 2048, sP, sP, sP, 0.03125f);

    // 10. output = scale_values @ preoutput (2048x1024x2048, NN) -> d_out
    gemm_tc<false><<<dim3(8, 16, 4), 256>>>(
        sc, po, out, 2048, 1024, 2048,
        2048, 1024, 1024, sP, sX, sX, 1.0f);
}